// round 2
// baseline (speedup 1.0000x reference)
#include <cuda_runtime.h>
#include <cstdint>

// Problem constants
// B=32, N=32, P0=16, P1=32, P2=16, R=3, D=8, V=2
// num_in = 112, RD = 24, P = N*(N-1) = 992
// out per b: 16 (null) + 32*32 (unary) + 32*31*16 (binary) = 16912

#define RD 24
#define NUMIN 112

typedef unsigned long long u64;

// -------- device scratch (no allocations allowed) --------
__device__ float g_BW[32 * 12 * 4];      // packed (w0,w1,c0,c1) per (kk, rdpair) for binary slices
__device__ float g_PU1[32 * 32 * RD];    // PN * U1 * sigmoid(or)  per (b,i,rd)
__device__ float g_U2[32 * 32 * RD];     // U2 per (b,j,rd)
__device__ float g_part0[32 * 32];       // per (b,i): prod_jj (1 - dis0)

// -------- packed f32x2 helpers (Blackwell) --------
__device__ __forceinline__ u64 pk2(float a, float b) {
    u64 r; asm("mov.b64 %0, {%1,%2};" : "=l"(r) : "f"(a), "f"(b)); return r;
}
__device__ __forceinline__ void upk2(u64 v, float& a, float& b) {
    asm("mov.b64 {%0,%1}, %2;" : "=f"(a), "=f"(b) : "l"(v));
}
__device__ __forceinline__ u64 fma2(u64 a, u64 b, u64 c) {
    u64 d; asm("fma.rn.f32x2 %0, %1, %2, %3;" : "=l"(d) : "l"(a), "l"(b), "l"(c)); return d;
}
__device__ __forceinline__ u64 mul2(u64 a, u64 b) {
    u64 d; asm("mul.rn.f32x2 %0, %1, %2;" : "=l"(d) : "l"(a), "l"(b)); return d;
}
__device__ __forceinline__ void lds_wc(u64& w, u64& c, uint32_t addr) {
    asm volatile("ld.shared.v2.u64 {%0,%1}, [%2];" : "=l"(w), "=l"(c) : "r"(addr));
}
__device__ __forceinline__ uint32_t smem_u32(const void* p) {
    uint32_t a;
    asm("{ .reg .u64 t; cvta.to.shared.u64 t, %1; cvt.u32.u64 %0, t; }" : "=r"(a) : "l"(p));
    return a;
}

// ============================================================================
// Kernel A: softmax of and_kernel -> (w,c); nullary+unary partial products;
//           block 0 publishes packed binary weights.
// grid = 32 (b), block = 768 (tid: i = t&31, rd = t>>5)
// ============================================================================
__global__ __launch_bounds__(768)
void kA(const float* __restrict__ nul, const float* __restrict__ una,
        const float* __restrict__ andk, const float* __restrict__ ork) {
    __shared__ float sW[RD * NUMIN];
    __shared__ float sC[RD * NUMIN];
    __shared__ float sU[32 * 32];   // [k][i] transposed
    __shared__ float sN[16];

    const int b = blockIdx.x;
    const int t = threadIdx.x;

    // softmax -> w = p0-p1, c = p1+p2
    for (int idx = t; idx < RD * NUMIN; idx += 768) {
        float a0 = andk[idx * 3 + 0];
        float a1 = andk[idx * 3 + 1];
        float a2 = andk[idx * 3 + 2];
        float m = fmaxf(a0, fmaxf(a1, a2));
        float e0 = expf(a0 - m), e1 = expf(a1 - m), e2 = expf(a2 - m);
        float inv = 1.0f / (e0 + e1 + e2);
        sW[idx] = (e0 - e1) * inv;
        sC[idx] = (e1 + e2) * inv;
    }
    // stage unary transposed: sU[k][i] = una[b, i, k]
    for (int idx = t; idx < 1024; idx += 768) {
        int i = idx >> 5, k = idx & 31;
        sU[k * 32 + i] = una[b * 1024 + idx];
    }
    if (t < 16) sN[t] = nul[b * 16 + t];
    __syncthreads();

    // block 0 publishes packed binary weights: (kk,rdp) -> (w_lo,w_hi,c_lo,c_hi)
    if (b == 0) {
        for (int idx = t; idx < 384; idx += 768) {
            int kk = idx / 12, rdp = idx % 12;
            int slice = (kk < 16) ? (80 + kk) : (96 + kk - 16);
            g_BW[idx * 4 + 0] = sW[(2 * rdp) * NUMIN + slice];
            g_BW[idx * 4 + 1] = sW[(2 * rdp + 1) * NUMIN + slice];
            g_BW[idx * 4 + 2] = sC[(2 * rdp) * NUMIN + slice];
            g_BW[idx * 4 + 3] = sC[(2 * rdp + 1) * NUMIN + slice];
        }
    }

    const int i  = t & 31;
    const int rd = t >> 5;           // 0..23
    const float* w = sW + rd * NUMIN;
    const float* c = sC + rd * NUMIN;

    float pn = 1.0f;
#pragma unroll
    for (int k = 0; k < 16; k++) pn *= fmaf(sN[k], w[k], c[k]);

    float u1 = 1.0f, u2 = 1.0f;
#pragma unroll
    for (int k = 0; k < 32; k++) {
        float x = sU[k * 32 + i];
        u1 *= fmaf(x, w[16 + k], c[16 + k]);
        u2 *= fmaf(x, w[48 + k], c[48 + k]);
    }
    // fold sigmoid(or_kernel) into the (b,i)-side partial product
    float okv = 1.0f / (1.0f + expf(-ork[rd]));
    g_PU1[(b * 32 + i) * RD + rd] = pn * u1 * okv;
    g_U2 [(b * 32 + i) * RD + rd] = u2;
}

// ============================================================================
// Kernel B: main conjunct/disjunct kernel.
// grid = (32 i, 32 b), block = 32 (lane = jj; lane 31 inactive for conjuncts)
// Writes binary output rows, unary output rows, g_part0 partials.
// ============================================================================
__global__ __launch_bounds__(32)
void kB(const float* __restrict__ binp, const float* __restrict__ una,
        float* __restrict__ out) {
    __shared__ float4 sBW[384];   // [kk][rdp] : (w0,w1,c0,c1)

    const int i = blockIdx.x;
    const int b = blockIdx.y;
    const int lane = threadIdx.x;

    // fill shared weights (6 KB)
    const float4* gbw = (const float4*)g_BW;
#pragma unroll
    for (int q = 0; q < 12; q++) sBW[lane + q * 32] = gbw[lane + q * 32];
    __syncwarp();

    const int  jj     = lane;
    const bool active = (jj < 31);
    const int  jj_s   = active ? jj : 0;
    const int  j      = jj_s + (jj_s >= i);       // actual second object
    const int  ip     = i - (jj_s < i);           // binary col index for (j,i)

    // load 32 x values: x1 = binp[b,i,jj,0..15], x2 = binp[b,j,ip,0..15]
    float xs[32];
    {
        const float4* p1 = (const float4*)(binp + (((size_t)b * 32 + i) * 31 + jj_s) * 16);
        const float4* p2 = (const float4*)(binp + (((size_t)b * 32 + j) * 31 + ip)  * 16);
#pragma unroll
        for (int q = 0; q < 4; q++) {
            float4 v = p1[q];
            xs[4 * q + 0] = v.x; xs[4 * q + 1] = v.y; xs[4 * q + 2] = v.z; xs[4 * q + 3] = v.w;
        }
#pragma unroll
        for (int q = 0; q < 4; q++) {
            float4 v = p2[q];
            xs[16 + 4 * q + 0] = v.x; xs[16 + 4 * q + 1] = v.y;
            xs[16 + 4 * q + 2] = v.z; xs[16 + 4 * q + 3] = v.w;
        }
    }

    // init accumulators: acc[rdp] = (PU1*U2) for rd = 2*rdp, 2*rdp+1
    const float* pu = g_PU1 + ((size_t)b * 32 + i) * RD;
    const float* u2 = g_U2  + ((size_t)b * 32 + j) * RD;
    u64 acc[12];
#pragma unroll
    for (int rdp = 0; rdp < 12; rdp++) {
        float lo = __ldg(pu + 2 * rdp)     * __ldg(u2 + 2 * rdp);
        float hi = __ldg(pu + 2 * rdp + 1) * __ldg(u2 + 2 * rdp + 1);
        acc[rdp] = pk2(lo, hi);
    }

    const uint32_t sb = smem_u32(sBW);
#pragma unroll
    for (int kk = 0; kk < 32; kk++) {
        u64 xx = pk2(xs[kk], xs[kk]);
#pragma unroll
        for (int rdp = 0; rdp < 12; rdp++) {
            u64 w, c;
            lds_wc(w, c, sb + (uint32_t)((kk * 12 + rdp) * 16));
            acc[rdp] = mul2(acc[rdp], fma2(xx, w, c));
        }
    }

    // unpack: tv[rd] = 1 - conj*ok  (ok already folded into PU1)
    float tv[24];
#pragma unroll
    for (int rdp = 0; rdp < 12; rdp++) {
        float lo, hi;
        upk2(acc[rdp], lo, hi);
        tv[2 * rdp]     = 1.0f - lo;
        tv[2 * rdp + 1] = 1.0f - hi;
    }
    // prod over D=8 per rule r (rd = r*8 + d)
    float pr0 = 1.0f, pr1 = 1.0f, pr2 = 1.0f;
#pragma unroll
    for (int d = 0; d < 8; d++) {
        pr0 *= tv[d];
        pr1 *= tv[8 + d];
        pr2 *= tv[16 + d];
    }

    // binary output row: copy channels 0..14, merge channel 15
    if (active) {
        float4 o[4];
#pragma unroll
        for (int q = 0; q < 4; q++) {
            o[q].x = xs[4 * q + 0]; o[q].y = xs[4 * q + 1];
            o[q].z = xs[4 * q + 2]; o[q].w = xs[4 * q + 3];
        }
        o[3].w = 1.0f - (1.0f - xs[15]) * pr2;   // merged last channel
        float4* ob = (float4*)(out + (size_t)b * 16912 + 1040 + (size_t)(i * 31 + jj) * 16);
#pragma unroll
        for (int q = 0; q < 4; q++) ob[q] = o[q];
    } else {
        pr0 = 1.0f;
        pr1 = 1.0f;
    }

    // warp product-reductions over jj
    float r0 = pr0, r1 = pr1;
#pragma unroll
    for (int s = 16; s > 0; s >>= 1) {
        r0 *= __shfl_xor_sync(0xFFFFFFFFu, r0, s);
        r1 *= __shfl_xor_sync(0xFFFFFFFFu, r1, s);
    }

    // unary output row: lane k copies channel k (k<31), lane 31 writes merged last
    float uk = una[(size_t)b * 1024 + i * 32 + lane];
    float uv = (lane < 31) ? uk : (1.0f - (1.0f - uk) * r1);
    out[(size_t)b * 16912 + 16 + i * 32 + lane] = uv;

    if (lane == 0) g_part0[b * 32 + i] = r0;
}

// ============================================================================
// Kernel C: nullary reduction + nullary output row.
// grid = 32 (b), block = 32
// ============================================================================
__global__ __launch_bounds__(32)
void kC(const float* __restrict__ nul, float* __restrict__ out) {
    const int b = blockIdx.x;
    const int lane = threadIdx.x;
    float p = g_part0[b * 32 + lane];
#pragma unroll
    for (int s = 16; s > 0; s >>= 1) p *= __shfl_xor_sync(0xFFFFFFFFu, p, s);
    if (lane < 16) {
        float v = nul[b * 16 + lane];
        out[(size_t)b * 16912 + lane] = (lane < 15) ? v : (1.0f - (1.0f - v) * p);
    }
}

// ============================================================================
extern "C" void kernel_launch(void* const* d_in, const int* in_sizes, int n_in,
                              void* d_out, int out_size) {
    // Identify the 5 inputs by rank order of element count (all distinct):
    //   ork (24) < nul (512) < andk (8064) < una (32768) < binp (507904)
    int order[5] = {0, 1, 2, 3, 4};
    // simple insertion sort of first 5 indices by size
    for (int a = 1; a < 5 && a < n_in; a++) {
        int key = order[a];
        int ks = in_sizes[key];
        int bpos = a - 1;
        while (bpos >= 0 && in_sizes[order[bpos]] > ks) {
            order[bpos + 1] = order[bpos];
            bpos--;
        }
        order[bpos + 1] = key;
    }
    const float* ork  = (const float*)d_in[order[0]];
    const float* nul  = (const float*)d_in[order[1]];
    const float* andk = (const float*)d_in[order[2]];
    const float* una  = (const float*)d_in[order[3]];
    const float* binp = (const float*)d_in[order[4]];
    float* out = (float*)d_out;

    kA<<<32, 768>>>(nul, una, andk, ork);
    kB<<<dim3(32, 32), 32>>>(binp, una, out);
    kC<<<32, 32>>>(nul, out);
}

// round 3
// speedup vs baseline: 1.1193x; 1.1193x over previous
#include <cuda_runtime.h>
#include <cstdint>

// Problem constants:
// B=32, N=32, P0=16, P1=32, P2=16, R=3, D=8, V=2
// num_in = 112, RD = 24
// out per b: 16 (null) + 1024 (unary) + 32*31*16 (binary) = 16912

#define RD 24
#define NUMIN 112

typedef unsigned long long u64;

// -------- device scratch (no allocations allowed) --------
__device__ float g_partB[32 * 4];          // per (b, ig) partial nullary product
__device__ unsigned int g_ctr = 0;         // last-block ticket counter

// -------- packed f32x2 helpers (Blackwell) --------
__device__ __forceinline__ u64 pk2(float a, float b) {
    u64 r; asm("mov.b64 %0, {%1,%2};" : "=l"(r) : "f"(a), "f"(b)); return r;
}
__device__ __forceinline__ void upk2(u64 v, float& a, float& b) {
    asm("mov.b64 {%0,%1}, %2;" : "=f"(a), "=f"(b) : "l"(v));
}
__device__ __forceinline__ u64 fma2(u64 a, u64 b, u64 c) {
    u64 d; asm("fma.rn.f32x2 %0, %1, %2, %3;" : "=l"(d) : "l"(a), "l"(b), "l"(c)); return d;
}
__device__ __forceinline__ u64 mul2(u64 a, u64 b) {
    u64 d; asm("mul.rn.f32x2 %0, %1, %2;" : "=l"(d) : "l"(a), "l"(b)); return d;
}
__device__ __forceinline__ void lds_wc(u64& w, u64& c, uint32_t addr) {
    asm volatile("ld.shared.v2.u64 {%0,%1}, [%2];" : "=l"(w), "=l"(c) : "r"(addr));
}
__device__ __forceinline__ uint32_t smem_u32(const void* p) {
    uint32_t a;
    asm("{ .reg .u64 t; cvta.to.shared.u64 t, %1; cvt.u32.u64 %0, t; }" : "=r"(a) : "l"(p));
    return a;
}

// ============================================================================
// Fused kernel: grid = (4 ig, 32 b), block = 256 (wid = i_loc, lane = jj).
// Each block: softmax weights -> shared; U2 for all j, PU1 for its 8 i's;
// main conjunct loop; unary/binary outputs; last block does nullary outputs.
// ============================================================================
__global__ __launch_bounds__(256, 1)
void kFused(const float* __restrict__ nul, const float* __restrict__ una,
            const float* __restrict__ binp, const float* __restrict__ andk,
            const float* __restrict__ ork, float* __restrict__ out) {
    __shared__ float  sW[RD * NUMIN];     // softmax p0-p1
    __shared__ float  sC[RD * NUMIN];     // softmax p1+p2
    __shared__ float  sU[32 * 32];        // unary transposed [k][i]
    __shared__ float4 sBW[384];           // packed binary weights [kk][rdp]
    __shared__ float  sU2[32 * 25];       // U2[j][rd], stride 25 (conflict-free)
    __shared__ float  sPU1[8 * 24];       // PN*U1*ok for local i's
    __shared__ float  sN[16];
    __shared__ float  sOK[24];
    __shared__ float  sWarpR0[8];
    __shared__ int    sIsLast;

    const int ig   = blockIdx.x;          // 0..3  (i group)
    const int b    = blockIdx.y;          // 0..31
    const int t    = threadIdx.x;         // 0..255
    const int wid  = t >> 5;              // 0..7  -> i_loc
    const int lane = t & 31;              // jj

    // ---- phase 1: softmax weights + staging ----
    for (int idx = t; idx < RD * NUMIN; idx += 256) {
        float a0 = andk[idx * 3 + 0];
        float a1 = andk[idx * 3 + 1];
        float a2 = andk[idx * 3 + 2];
        float m = fmaxf(a0, fmaxf(a1, a2));
        float e0 = expf(a0 - m), e1 = expf(a1 - m), e2 = expf(a2 - m);
        float inv = 1.0f / (e0 + e1 + e2);
        sW[idx] = (e0 - e1) * inv;
        sC[idx] = (e1 + e2) * inv;
    }
    for (int idx = t; idx < 1024; idx += 256) {
        int i = idx >> 5, k = idx & 31;
        sU[k * 32 + i] = una[b * 1024 + idx];
    }
    if (t < 16) sN[t] = nul[b * 16 + t];
    else if (t >= 32 && t < 56) sOK[t - 32] = 1.0f / (1.0f + expf(-ork[t - 32]));
    __syncthreads();

    // ---- phase 2a: packed binary weights ----
    for (int idx = t; idx < 384; idx += 256) {
        int kk = idx / 12, rdp = idx % 12;
        int slice = (kk < 16) ? (80 + kk) : (96 + kk - 16);
        float4 v;
        v.x = sW[(2 * rdp)     * NUMIN + slice];
        v.y = sW[(2 * rdp + 1) * NUMIN + slice];
        v.z = sC[(2 * rdp)     * NUMIN + slice];
        v.w = sC[(2 * rdp + 1) * NUMIN + slice];
        sBW[idx] = v;
    }
    // ---- phase 2b: U2 for all (j, rd) ----
    for (int item = t; item < 768; item += 256) {
        int j = item & 31, rd = item >> 5;
        const float* w = sW + rd * NUMIN;
        const float* c = sC + rd * NUMIN;
        float u2 = 1.0f;
#pragma unroll
        for (int k = 0; k < 32; k++)
            u2 *= fmaf(sU[k * 32 + j], w[48 + k], c[48 + k]);
        sU2[j * 25 + rd] = u2;
    }
    // ---- phase 2c: PU1 for local 8 i's ----
    if (t < 192) {
        int i_loc = t & 7, rd = t >> 3;
        int i = ig * 8 + i_loc;
        const float* w = sW + rd * NUMIN;
        const float* c = sC + rd * NUMIN;
        float pn = 1.0f;
#pragma unroll
        for (int k = 0; k < 16; k++) pn *= fmaf(sN[k], w[k], c[k]);
        float u1 = 1.0f;
#pragma unroll
        for (int k = 0; k < 32; k++) u1 *= fmaf(sU[k * 32 + i], w[16 + k], c[16 + k]);
        sPU1[i_loc * 24 + rd] = pn * u1 * sOK[rd];
    }
    __syncthreads();

    // ---- main loop: thread = (i = ig*8+wid, jj = lane) ----
    const int  i      = ig * 8 + wid;
    const int  jj     = lane;
    const bool active = (jj < 31);
    const int  jj_s   = active ? jj : 0;
    const int  j      = jj_s + (jj_s >= i);     // second object index
    const int  ip     = i - (jj_s < i);         // binary col index for (j,i)

    float xs[32];
    {
        const float4* p1 = (const float4*)(binp + (((size_t)b * 32 + i) * 31 + jj_s) * 16);
        const float4* p2 = (const float4*)(binp + (((size_t)b * 32 + j) * 31 + ip)   * 16);
#pragma unroll
        for (int q = 0; q < 4; q++) {
            float4 v = p1[q];
            xs[4 * q + 0] = v.x; xs[4 * q + 1] = v.y; xs[4 * q + 2] = v.z; xs[4 * q + 3] = v.w;
        }
#pragma unroll
        for (int q = 0; q < 4; q++) {
            float4 v = p2[q];
            xs[16 + 4 * q + 0] = v.x; xs[16 + 4 * q + 1] = v.y;
            xs[16 + 4 * q + 2] = v.z; xs[16 + 4 * q + 3] = v.w;
        }
    }

    // acc init: PU1(b,i,rd) * U2(b,j,rd), rd paired
    u64 acc[12];
#pragma unroll
    for (int rdp = 0; rdp < 12; rdp++) {
        float lo = sPU1[wid * 24 + 2 * rdp]     * sU2[j * 25 + 2 * rdp];
        float hi = sPU1[wid * 24 + 2 * rdp + 1] * sU2[j * 25 + 2 * rdp + 1];
        acc[rdp] = pk2(lo, hi);
    }

    const uint32_t sb = smem_u32(sBW);
#pragma unroll
    for (int kk = 0; kk < 32; kk++) {
        u64 xx = pk2(xs[kk], xs[kk]);
#pragma unroll
        for (int rdp = 0; rdp < 12; rdp++) {
            u64 w, c;
            lds_wc(w, c, sb + (uint32_t)((kk * 12 + rdp) * 16));
            acc[rdp] = mul2(acc[rdp], fma2(xx, w, c));
        }
    }

    // tv[rd] = 1 - conj*ok ; rule products over D=8
    float tv[24];
#pragma unroll
    for (int rdp = 0; rdp < 12; rdp++) {
        float lo, hi;
        upk2(acc[rdp], lo, hi);
        tv[2 * rdp]     = 1.0f - lo;
        tv[2 * rdp + 1] = 1.0f - hi;
    }
    float pr0 = 1.0f, pr1 = 1.0f, pr2 = 1.0f;
#pragma unroll
    for (int d = 0; d < 8; d++) {
        pr0 *= tv[d];
        pr1 *= tv[8 + d];
        pr2 *= tv[16 + d];
    }

    // binary output row (channels 0..14 copy, channel 15 merged)
    if (active) {
        float4 o[4];
#pragma unroll
        for (int q = 0; q < 4; q++) {
            o[q].x = xs[4 * q + 0]; o[q].y = xs[4 * q + 1];
            o[q].z = xs[4 * q + 2]; o[q].w = xs[4 * q + 3];
        }
        o[3].w = 1.0f - (1.0f - xs[15]) * pr2;
        float4* ob = (float4*)(out + (size_t)b * 16912 + 1040 + (size_t)(i * 31 + jj) * 16);
#pragma unroll
        for (int q = 0; q < 4; q++) ob[q] = o[q];
    } else {
        pr0 = 1.0f;
        pr1 = 1.0f;
    }

    // warp product-reductions over jj
    float r0 = pr0, r1 = pr1;
#pragma unroll
    for (int s = 16; s > 0; s >>= 1) {
        r0 *= __shfl_xor_sync(0xFFFFFFFFu, r0, s);
        r1 *= __shfl_xor_sync(0xFFFFFFFFu, r1, s);
    }

    // unary output row
    {
        float uk = una[(size_t)b * 1024 + i * 32 + lane];
        float uv = (lane < 31) ? uk : (1.0f - (1.0f - uk) * r1);
        out[(size_t)b * 16912 + 16 + i * 32 + lane] = uv;
    }

    if (lane == 0) sWarpR0[wid] = r0;
    __syncthreads();

    // ---- last-block nullary epilogue ----
    if (t == 0) {
        float p = 1.0f;
#pragma unroll
        for (int w = 0; w < 8; w++) p *= sWarpR0[w];
        __stcg(&g_partB[b * 4 + ig], p);
        __threadfence();
        unsigned int ticket = atomicAdd(&g_ctr, 1u);
        sIsLast = (ticket == 127u) ? 1 : 0;
    }
    __syncthreads();

    if (sIsLast) {
        __threadfence();   // acquire side: order partial reads after ticket
        for (int item = t; item < 512; item += 256) {
            int bb = item >> 4, c = item & 15;
            float v = nul[bb * 16 + c];
            if (c == 15) {
                float p = __ldcg(&g_partB[bb * 4 + 0]) * __ldcg(&g_partB[bb * 4 + 1]) *
                          __ldcg(&g_partB[bb * 4 + 2]) * __ldcg(&g_partB[bb * 4 + 3]);
                v = 1.0f - (1.0f - v) * p;
            }
            out[(size_t)bb * 16912 + c] = v;
        }
        if (t == 0) atomicExch(&g_ctr, 0u);   // reset for next graph replay
    }
}

// ============================================================================
extern "C" void kernel_launch(void* const* d_in, const int* in_sizes, int n_in,
                              void* d_out, int out_size) {
    // Identify the 5 inputs by rank order of element count (all distinct):
    //   ork (24) < nul (512) < andk (8064) < una (32768) < binp (507904)
    int order[5] = {0, 1, 2, 3, 4};
    for (int a = 1; a < 5 && a < n_in; a++) {
        int key = order[a];
        int ks = in_sizes[key];
        int bpos = a - 1;
        while (bpos >= 0 && in_sizes[order[bpos]] > ks) {
            order[bpos + 1] = order[bpos];
            bpos--;
        }
        order[bpos + 1] = key;
    }
    const float* ork  = (const float*)d_in[order[0]];
    const float* nul  = (const float*)d_in[order[1]];
    const float* andk = (const float*)d_in[order[2]];
    const float* una  = (const float*)d_in[order[3]];
    const float* binp = (const float*)d_in[order[4]];
    float* out = (float*)d_out;

    kFused<<<dim3(4, 32), 256>>>(nul, una, binp, andk, ork, out);
}

// round 4
// speedup vs baseline: 1.1214x; 1.0019x over previous
#include <cuda_runtime.h>
#include <cstdint>

// Problem constants:
// B=32, N=32, P0=16, P1=32, P2=16, R=3, D=8, V=2
// num_in = 112, RD = 24
// out per b: 16 (null) + 1024 (unary) + 32*31*16 (binary) = 16912

#define RD 24
#define NUMIN 112

typedef unsigned long long u64;

// -------- device scratch (no allocations allowed) --------
__device__ float g_partB[32 * 4];          // per (b, ig) partial nullary product
__device__ unsigned int g_ctr = 0;         // last-block ticket counter

// -------- packed f32x2 helpers (Blackwell) --------
__device__ __forceinline__ u64 pk2(float a, float b) {
    u64 r; asm("mov.b64 %0, {%1,%2};" : "=l"(r) : "f"(a), "f"(b)); return r;
}
__device__ __forceinline__ void upk2(u64 v, float& a, float& b) {
    asm("mov.b64 {%0,%1}, %2;" : "=f"(a), "=f"(b) : "l"(v));
}
__device__ __forceinline__ u64 fma2(u64 a, u64 b, u64 c) {
    u64 d; asm("fma.rn.f32x2 %0, %1, %2, %3;" : "=l"(d) : "l"(a), "l"(b), "l"(c)); return d;
}
__device__ __forceinline__ u64 mul2(u64 a, u64 b) {
    u64 d; asm("mul.rn.f32x2 %0, %1, %2;" : "=l"(d) : "l"(a), "l"(b)); return d;
}
__device__ __forceinline__ void lds_wc(u64& w, u64& c, uint32_t addr) {
    asm volatile("ld.shared.v2.u64 {%0,%1}, [%2];" : "=l"(w), "=l"(c) : "r"(addr));
}
__device__ __forceinline__ uint32_t smem_u32(const void* p) {
    uint32_t a;
    asm("{ .reg .u64 t; cvta.to.shared.u64 t, %1; cvt.u32.u64 %0, t; }" : "=r"(a) : "l"(p));
    return a;
}

// ============================================================================
// Fused kernel: grid = (4 ig, 32 b), block = 256 (wid = i_loc, lane = jj).
// ============================================================================
__global__ __launch_bounds__(256, 1)
void kFused(const float* __restrict__ nul, const float* __restrict__ una,
            const float* __restrict__ binp, const float* __restrict__ andk,
            const float* __restrict__ ork, float* __restrict__ out) {
    __shared__ float2 sWC[RD * NUMIN];    // (w = p0-p1, c = p1+p2)
    __shared__ float  sU[32 * 32];        // unary transposed [k][i]
    __shared__ float4 sBW[384];           // packed binary weights [kk][rdp]
    __shared__ float  sU2[32 * 25];       // U2[j][rd], stride 25
    __shared__ float  sPU1[8 * 24];       // PN*U1*ok for local i's
    __shared__ float  sN[16];
    __shared__ float  sOK[24];
    __shared__ float  sWarpR0[8];
    __shared__ int    sIsLast;

    const int ig   = blockIdx.x;          // 0..3  (i group)
    const int b    = blockIdx.y;          // 0..31
    const int t    = threadIdx.x;         // 0..255
    const int wid  = t >> 5;              // 0..7  -> i_loc
    const int lane = t & 31;              // jj

    // ---- hoisted global loads: issue LDGs before any shared-phase compute ----
    const int  i      = ig * 8 + wid;
    const int  jj     = lane;
    const bool active = (jj < 31);
    const int  jj_s   = active ? jj : 0;
    const int  j      = jj_s + (jj_s >= i);     // second object index
    const int  ip     = i - (jj_s < i);         // binary col index for (j,i)

    float xs[32];
    {
        const float4* p1 = (const float4*)(binp + (((size_t)b * 32 + i) * 31 + jj_s) * 16);
        const float4* p2 = (const float4*)(binp + (((size_t)b * 32 + j) * 31 + ip)   * 16);
        float4 va[4], vb[4];
#pragma unroll
        for (int q = 0; q < 4; q++) va[q] = p1[q];
#pragma unroll
        for (int q = 0; q < 4; q++) vb[q] = p2[q];
#pragma unroll
        for (int q = 0; q < 4; q++) {
            xs[4 * q + 0] = va[q].x; xs[4 * q + 1] = va[q].y;
            xs[4 * q + 2] = va[q].z; xs[4 * q + 3] = va[q].w;
            xs[16 + 4 * q + 0] = vb[q].x; xs[16 + 4 * q + 1] = vb[q].y;
            xs[16 + 4 * q + 2] = vb[q].z; xs[16 + 4 * q + 3] = vb[q].w;
        }
    }
    const float uk = una[(size_t)b * 1024 + i * 32 + lane];   // unary epilogue value

    // ---- phase 1: softmax weights (fast math) + staging ----
    for (int idx = t; idx < RD * NUMIN; idx += 256) {
        float a0 = andk[idx * 3 + 0];
        float a1 = andk[idx * 3 + 1];
        float a2 = andk[idx * 3 + 2];
        float e0 = __expf(a0), e1 = __expf(a1), e2 = __expf(a2);
        float inv = __fdividef(1.0f, e0 + e1 + e2);
        sWC[idx] = make_float2((e0 - e1) * inv, (e1 + e2) * inv);
    }
    for (int idx = t; idx < 1024; idx += 256) {
        int ii = idx >> 5, k = idx & 31;
        sU[k * 32 + ii] = una[b * 1024 + idx];
    }
    if (t < 16) sN[t] = nul[b * 16 + t];
    else if (t >= 32 && t < 56) {
        float x = ork[t - 32];
        sOK[t - 32] = __fdividef(1.0f, 1.0f + __expf(-x));
    }
    __syncthreads();

    // ---- phase 2a: packed binary weights ----
    for (int idx = t; idx < 384; idx += 256) {
        int kk = idx / 12, rdp = idx % 12;
        int slice = (kk < 16) ? (80 + kk) : (96 + kk - 16);
        float2 lo = sWC[(2 * rdp)     * NUMIN + slice];
        float2 hi = sWC[(2 * rdp + 1) * NUMIN + slice];
        sBW[idx] = make_float4(lo.x, hi.x, lo.y, hi.y);
    }
    // ---- phase 2b: U2 for all (j, rd): 3 independent chains per thread ----
#pragma unroll
    for (int it = 0; it < 3; it++) {
        int item = t + it * 256;
        int jx = item & 31, rd = item >> 5;
        const float2* wc = sWC + rd * NUMIN + 48;
        float u2 = 1.0f;
#pragma unroll
        for (int k = 0; k < 32; k++) {
            float2 p = wc[k];
            u2 *= fmaf(sU[k * 32 + jx], p.x, p.y);
        }
        sU2[jx * 25 + rd] = u2;
    }
    // ---- phase 2c: PU1 for local 8 i's ----
    if (t < 192) {
        int i_loc = t & 7, rd = t >> 3;
        int ii = ig * 8 + i_loc;
        const float2* wc = sWC + rd * NUMIN;
        float pn = 1.0f;
#pragma unroll
        for (int k = 0; k < 16; k++) { float2 p = wc[k]; pn *= fmaf(sN[k], p.x, p.y); }
        float u1 = 1.0f;
#pragma unroll
        for (int k = 0; k < 32; k++) { float2 p = wc[16 + k]; u1 *= fmaf(sU[k * 32 + ii], p.x, p.y); }
        sPU1[i_loc * 24 + rd] = pn * u1 * sOK[rd];
    }
    __syncthreads();

    // ---- main loop ----
    u64 acc[12];
#pragma unroll
    for (int rdp = 0; rdp < 12; rdp++) {
        float lo = sPU1[wid * 24 + 2 * rdp]     * sU2[j * 25 + 2 * rdp];
        float hi = sPU1[wid * 24 + 2 * rdp + 1] * sU2[j * 25 + 2 * rdp + 1];
        acc[rdp] = pk2(lo, hi);
    }

    const uint32_t sb = smem_u32(sBW);
#pragma unroll
    for (int kk = 0; kk < 32; kk++) {
        u64 xx = pk2(xs[kk], xs[kk]);
#pragma unroll
        for (int rdp = 0; rdp < 12; rdp++) {
            u64 w, c;
            lds_wc(w, c, sb + (uint32_t)((kk * 12 + rdp) * 16));
            acc[rdp] = mul2(acc[rdp], fma2(xx, w, c));
        }
    }

    // tv[rd] = 1 - conj*ok ; rule products over D=8
    float tv[24];
#pragma unroll
    for (int rdp = 0; rdp < 12; rdp++) {
        float lo, hi;
        upk2(acc[rdp], lo, hi);
        tv[2 * rdp]     = 1.0f - lo;
        tv[2 * rdp + 1] = 1.0f - hi;
    }
    float pr0 = 1.0f, pr1 = 1.0f, pr2 = 1.0f;
#pragma unroll
    for (int d = 0; d < 8; d++) {
        pr0 *= tv[d];
        pr1 *= tv[8 + d];
        pr2 *= tv[16 + d];
    }

    // binary output row (channels 0..14 copy, channel 15 merged)
    if (active) {
        float4 o[4];
#pragma unroll
        for (int q = 0; q < 4; q++) {
            o[q].x = xs[4 * q + 0]; o[q].y = xs[4 * q + 1];
            o[q].z = xs[4 * q + 2]; o[q].w = xs[4 * q + 3];
        }
        o[3].w = 1.0f - (1.0f - xs[15]) * pr2;
        float4* ob = (float4*)(out + (size_t)b * 16912 + 1040 + (size_t)(i * 31 + jj) * 16);
#pragma unroll
        for (int q = 0; q < 4; q++) ob[q] = o[q];
    } else {
        pr0 = 1.0f;
        pr1 = 1.0f;
    }

    // warp product-reductions over jj
    float r0 = pr0, r1 = pr1;
#pragma unroll
    for (int s = 16; s > 0; s >>= 1) {
        r0 *= __shfl_xor_sync(0xFFFFFFFFu, r0, s);
        r1 *= __shfl_xor_sync(0xFFFFFFFFu, r1, s);
    }

    // unary output row
    {
        float uv = (lane < 31) ? uk : (1.0f - (1.0f - uk) * r1);
        out[(size_t)b * 16912 + 16 + i * 32 + lane] = uv;
    }

    if (lane == 0) sWarpR0[wid] = r0;
    __syncthreads();

    // ---- last-block nullary epilogue ----
    if (t == 0) {
        float p = 1.0f;
#pragma unroll
        for (int w = 0; w < 8; w++) p *= sWarpR0[w];
        __stcg(&g_partB[b * 4 + ig], p);
        __threadfence();
        unsigned int ticket = atomicAdd(&g_ctr, 1u);
        sIsLast = (ticket == 127u) ? 1 : 0;
    }
    __syncthreads();

    if (sIsLast) {
        __threadfence();
        for (int item = t; item < 512; item += 256) {
            int bb = item >> 4, c = item & 15;
            float v = nul[bb * 16 + c];
            if (c == 15) {
                float p = __ldcg(&g_partB[bb * 4 + 0]) * __ldcg(&g_partB[bb * 4 + 1]) *
                          __ldcg(&g_partB[bb * 4 + 2]) * __ldcg(&g_partB[bb * 4 + 3]);
                v = 1.0f - (1.0f - v) * p;
            }
            out[(size_t)bb * 16912 + c] = v;
        }
        if (t == 0) atomicExch(&g_ctr, 0u);
    }
}

// ============================================================================
extern "C" void kernel_launch(void* const* d_in, const int* in_sizes, int n_in,
                              void* d_out, int out_size) {
    // Identify the 5 inputs by rank order of element count (all distinct):
    //   ork (24) < nul (512) < andk (8064) < una (32768) < binp (507904)
    int order[5] = {0, 1, 2, 3, 4};
    for (int a = 1; a < 5 && a < n_in; a++) {
        int key = order[a];
        int ks = in_sizes[key];
        int bpos = a - 1;
        while (bpos >= 0 && in_sizes[order[bpos]] > ks) {
            order[bpos + 1] = order[bpos];
            bpos--;
        }
        order[bpos + 1] = key;
    }
    const float* ork  = (const float*)d_in[order[0]];
    const float* nul  = (const float*)d_in[order[1]];
    const float* andk = (const float*)d_in[order[2]];
    const float* una  = (const float*)d_in[order[3]];
    const float* binp = (const float*)d_in[order[4]];
    float* out = (float*)d_out;

    kFused<<<dim3(4, 32), 256>>>(nul, una, binp, andk, ork, out);
}

// round 5
// speedup vs baseline: 1.2710x; 1.1333x over previous
#include <cuda_runtime.h>
#include <cstdint>

// Problem constants:
// B=32, N=32, P0=16, P1=32, P2=16, R=3, D=8, V=2
// num_in = 112, RD = 24
// out per b: 16 (null) + 1024 (unary) + 32*31*16 (binary) = 16912

#define RD 24
#define NUMIN 112

typedef unsigned long long u64;

// -------- device scratch --------
__device__ float g_partB[32 * 4];
__device__ unsigned int g_ctr = 0;

// -------- packed f32x2 helpers (Blackwell) --------
__device__ __forceinline__ u64 pk2(float a, float b) {
    u64 r; asm("mov.b64 %0, {%1,%2};" : "=l"(r) : "f"(a), "f"(b)); return r;
}
__device__ __forceinline__ void upk2(u64 v, float& a, float& b) {
    asm("mov.b64 {%0,%1}, %2;" : "=f"(a), "=f"(b) : "l"(v));
}
__device__ __forceinline__ u64 fma2(u64 a, u64 b, u64 c) {
    u64 d; asm("fma.rn.f32x2 %0, %1, %2, %3;" : "=l"(d) : "l"(a), "l"(b), "l"(c)); return d;
}
__device__ __forceinline__ u64 mul2(u64 a, u64 b) {
    u64 d; asm("mul.rn.f32x2 %0, %1, %2;" : "=l"(d) : "l"(a), "l"(b)); return d;
}
__device__ __forceinline__ void lds_wc(u64& w, u64& c, uint32_t addr) {
    asm volatile("ld.shared.v2.u64 {%0,%1}, [%2];" : "=l"(w), "=l"(c) : "r"(addr));
}
__device__ __forceinline__ uint32_t smem_u32(const void* p) {
    uint32_t a;
    asm("{ .reg .u64 t; cvta.to.shared.u64 t, %1; cvt.u32.u64 %0, t; }" : "=r"(a) : "l"(p));
    return a;
}

// ============================================================================
// Fused kernel: grid = (4 ig, 32 b), block = 512.
// wid 0..15: half = wid>>3, i_loc = wid&7, lane = jj.
// half0: kk 0..15 (x1 row) + epilogue; half1: kk 16..31 (x2 row).
// ============================================================================
__global__ __launch_bounds__(512, 1)
void kFused(const float* __restrict__ nul, const float* __restrict__ una,
            const float* __restrict__ binp, const float* __restrict__ andk,
            const float* __restrict__ ork, float* __restrict__ out) {
    // region A: phases 1-2 use sWC (21504 B) + sU (4096 B); main-loop exchange
    // reuses the same bytes as sAcc (24576 B). All uses separated by barriers.
    __shared__ __align__(16) char regA[25600];
    float2* sWC  = (float2*)regA;             // [RD*NUMIN] (w,c)
    float*  sU   = (float*)(regA + 21504);    // [32*32] unary transposed [k][i]
    u64*    sAcc = (u64*)regA;                // [8][32][12] half1 partials

    __shared__ float4 sBW[384];               // packed binary weights [kk][rdp]
    __shared__ float  sU2[32 * 25];           // U2[j][rd]
    __shared__ float  sPU1[8 * 24];           // PN*U1*ok for local i's
    __shared__ float  sN[16];
    __shared__ float  sOK[24];
    __shared__ float  sWarpR0[8];
    __shared__ int    sIsLast;

    const int ig   = blockIdx.x;
    const int b    = blockIdx.y;
    const int t    = threadIdx.x;             // 0..511
    const int wid  = t >> 5;                  // 0..15
    const int lane = t & 31;
    const int half  = wid >> 3;               // 0 or 1
    const int i_loc = wid & 7;
    const int i     = ig * 8 + i_loc;

    const int  jj     = lane;
    const bool active = (jj < 31);
    const int  jj_s   = active ? jj : 0;
    const int  j      = jj_s + (jj_s >= i);   // second object index
    const int  ip     = i - (jj_s < i);       // binary col index for (j,i)

    // ---- hoisted global loads: this half's 16 x-values ----
    float xs[16];
    {
        const size_t row = half ? (((size_t)b * 32 + j) * 31 + ip)
                                : (((size_t)b * 32 + i) * 31 + jj_s);
        const float4* p = (const float4*)(binp + row * 16);
        float4 v[4];
#pragma unroll
        for (int q = 0; q < 4; q++) v[q] = p[q];
#pragma unroll
        for (int q = 0; q < 4; q++) {
            xs[4 * q + 0] = v[q].x; xs[4 * q + 1] = v[q].y;
            xs[4 * q + 2] = v[q].z; xs[4 * q + 3] = v[q].w;
        }
    }
    const float uk = (half == 0) ? una[(size_t)b * 1024 + i * 32 + lane] : 0.0f;

    // ---- phase 1: softmax weights (fast math) + staging ----
    for (int idx = t; idx < RD * NUMIN; idx += 512) {
        float a0 = andk[idx * 3 + 0];
        float a1 = andk[idx * 3 + 1];
        float a2 = andk[idx * 3 + 2];
        float e0 = __expf(a0), e1 = __expf(a1), e2 = __expf(a2);
        float inv = __fdividef(1.0f, e0 + e1 + e2);
        sWC[idx] = make_float2((e0 - e1) * inv, (e1 + e2) * inv);
    }
    for (int idx = t; idx < 1024; idx += 512) {
        int ii = idx >> 5, k = idx & 31;
        sU[k * 32 + ii] = una[b * 1024 + idx];
    }
    if (t < 16) sN[t] = nul[b * 16 + t];
    else if (t >= 32 && t < 56) {
        float x = ork[t - 32];
        sOK[t - 32] = __fdividef(1.0f, 1.0f + __expf(-x));
    }
    __syncthreads();

    // ---- phase 2a: packed binary weights ----
    if (t < 384) {
        int kk = t / 12, rdp = t % 12;
        int slice = (kk < 16) ? (80 + kk) : (96 + kk - 16);
        float2 lo = sWC[(2 * rdp)     * NUMIN + slice];
        float2 hi = sWC[(2 * rdp + 1) * NUMIN + slice];
        sBW[t] = make_float4(lo.x, hi.x, lo.y, hi.y);
    }
    // ---- phase 2b: U2 for all (j, rd), 4-way split product chains ----
    for (int item = t; item < 768; item += 512) {
        int jx = item & 31, rd = item >> 5;
        const float2* wc = sWC + rd * NUMIN + 48;
        float pa = 1.0f, pb = 1.0f, pc = 1.0f, pd = 1.0f;
#pragma unroll
        for (int k = 0; k < 8; k++) {
            float2 w0 = wc[k],      w1 = wc[8 + k];
            float2 w2 = wc[16 + k], w3 = wc[24 + k];
            pa *= fmaf(sU[k * 32 + jx],        w0.x, w0.y);
            pb *= fmaf(sU[(8 + k) * 32 + jx],  w1.x, w1.y);
            pc *= fmaf(sU[(16 + k) * 32 + jx], w2.x, w2.y);
            pd *= fmaf(sU[(24 + k) * 32 + jx], w3.x, w3.y);
        }
        sU2[jx * 25 + rd] = (pa * pb) * (pc * pd);
    }
    // ---- phase 2c: PU1 for local 8 i's ----
    if (t < 192) {
        int il = t & 7, rd = t >> 3;
        int ii = ig * 8 + il;
        const float2* wc = sWC + rd * NUMIN;
        float pa = 1.0f, pb = 1.0f, pc = 1.0f, pd = 1.0f;
#pragma unroll
        for (int k = 0; k < 8; k++) {
            float2 w0 = wc[k], w1 = wc[8 + k];
            pa *= fmaf(sN[k],     w0.x, w0.y);
            pb *= fmaf(sN[8 + k], w1.x, w1.y);
        }
#pragma unroll
        for (int k = 0; k < 16; k++) {
            float2 w0 = wc[16 + k], w1 = wc[32 + k];
            pc *= fmaf(sU[k * 32 + ii],        w0.x, w0.y);
            pd *= fmaf(sU[(16 + k) * 32 + ii], w1.x, w1.y);
        }
        sPU1[il * 24 + rd] = ((pa * pb) * (pc * pd)) * sOK[rd];
    }
    __syncthreads();

    // ---- main loop: 16 kk per half ----
    u64 acc[12];
    if (half == 0) {
#pragma unroll
        for (int rdp = 0; rdp < 12; rdp++) {
            float lo = sPU1[i_loc * 24 + 2 * rdp]     * sU2[j * 25 + 2 * rdp];
            float hi = sPU1[i_loc * 24 + 2 * rdp + 1] * sU2[j * 25 + 2 * rdp + 1];
            acc[rdp] = pk2(lo, hi);
        }
    } else {
        u64 one = pk2(1.0f, 1.0f);
#pragma unroll
        for (int rdp = 0; rdp < 12; rdp++) acc[rdp] = one;
    }

    const uint32_t sb = smem_u32(sBW) + (uint32_t)(half * 16 * 12 * 16);
#pragma unroll
    for (int kl = 0; kl < 16; kl++) {
        u64 xx = pk2(xs[kl], xs[kl]);
#pragma unroll
        for (int rdp = 0; rdp < 12; rdp++) {
            u64 w, c;
            lds_wc(w, c, sb + (uint32_t)((kl * 12 + rdp) * 16));
            acc[rdp] = mul2(acc[rdp], fma2(xx, w, c));
        }
    }

    // ---- exchange: half1 -> shared (overlaps dead sWC/sU region) ----
    __syncthreads();   // ensure all phase-2 reads of sWC/sU are done
    if (half == 1) {
        u64* dst = sAcc + ((size_t)i_loc * 32 + jj) * 12;
#pragma unroll
        for (int rdp = 0; rdp < 12; rdp++) dst[rdp] = acc[rdp];
    }
    __syncthreads();

    if (half == 0) {
        const u64* src = sAcc + ((size_t)i_loc * 32 + jj) * 12;
        float tv[24];
#pragma unroll
        for (int rdp = 0; rdp < 12; rdp++) {
            u64 m = mul2(acc[rdp], src[rdp]);
            float lo, hi;
            upk2(m, lo, hi);
            tv[2 * rdp]     = 1.0f - lo;
            tv[2 * rdp + 1] = 1.0f - hi;
        }
        float pr0 = 1.0f, pr1 = 1.0f, pr2 = 1.0f;
#pragma unroll
        for (int d = 0; d < 8; d++) {
            pr0 *= tv[d];
            pr1 *= tv[8 + d];
            pr2 *= tv[16 + d];
        }

        // binary output row (channels 0..14 copy, channel 15 merged)
        if (active) {
            float4 o[4];
#pragma unroll
            for (int q = 0; q < 4; q++) {
                o[q].x = xs[4 * q + 0]; o[q].y = xs[4 * q + 1];
                o[q].z = xs[4 * q + 2]; o[q].w = xs[4 * q + 3];
            }
            o[3].w = 1.0f - (1.0f - xs[15]) * pr2;
            float4* ob = (float4*)(out + (size_t)b * 16912 + 1040 + (size_t)(i * 31 + jj) * 16);
#pragma unroll
            for (int q = 0; q < 4; q++) ob[q] = o[q];
        } else {
            pr0 = 1.0f;
            pr1 = 1.0f;
        }

        // warp product-reductions over jj
        float r0 = pr0, r1 = pr1;
#pragma unroll
        for (int s = 16; s > 0; s >>= 1) {
            r0 *= __shfl_xor_sync(0xFFFFFFFFu, r0, s);
            r1 *= __shfl_xor_sync(0xFFFFFFFFu, r1, s);
        }

        // unary output row
        float uv = (lane < 31) ? uk : (1.0f - (1.0f - uk) * r1);
        out[(size_t)b * 16912 + 16 + i * 32 + lane] = uv;

        if (lane == 0) sWarpR0[i_loc] = r0;
    }
    __syncthreads();

    // ---- last-block nullary epilogue ----
    if (t == 0) {
        float p = 1.0f;
#pragma unroll
        for (int w = 0; w < 8; w++) p *= sWarpR0[w];
        __stcg(&g_partB[b * 4 + ig], p);
        __threadfence();
        unsigned int ticket = atomicAdd(&g_ctr, 1u);
        sIsLast = (ticket == 127u) ? 1 : 0;
    }
    __syncthreads();

    if (sIsLast) {
        __threadfence();
        if (t < 512) {
            int bb = t >> 4, c = t & 15;
            float v = nul[bb * 16 + c];
            if (c == 15) {
                float p = __ldcg(&g_partB[bb * 4 + 0]) * __ldcg(&g_partB[bb * 4 + 1]) *
                          __ldcg(&g_partB[bb * 4 + 2]) * __ldcg(&g_partB[bb * 4 + 3]);
                v = 1.0f - (1.0f - v) * p;
            }
            out[(size_t)bb * 16912 + c] = v;
        }
        if (t == 0) atomicExch(&g_ctr, 0u);
    }
}

// ============================================================================
extern "C" void kernel_launch(void* const* d_in, const int* in_sizes, int n_in,
                              void* d_out, int out_size) {
    // Identify the 5 inputs by rank order of element count (all distinct):
    //   ork (24) < nul (512) < andk (8064) < una (32768) < binp (507904)
    int order[5] = {0, 1, 2, 3, 4};
    for (int a = 1; a < 5 && a < n_in; a++) {
        int key = order[a];
        int ks = in_sizes[key];
        int bpos = a - 1;
        while (bpos >= 0 && in_sizes[order[bpos]] > ks) {
            order[bpos + 1] = order[bpos];
            bpos--;
        }
        order[bpos + 1] = key;
    }
    const float* ork  = (const float*)d_in[order[0]];
    const float* nul  = (const float*)d_in[order[1]];
    const float* andk = (const float*)d_in[order[2]];
    const float* una  = (const float*)d_in[order[3]];
    const float* binp = (const float*)d_in[order[4]];
    float* out = (float*)d_out;

    kFused<<<dim3(4, 32), 512>>>(nul, una, binp, andk, ork, out);
}